// round 1
// baseline (speedup 1.0000x reference)
#include <cuda_runtime.h>
#include <math.h>

// ---------------------------------------------------------------------------
// FNO2d: B=16, Cin=5, S=128, W=64 channels, M=16 modes, D=4 layers, PAD=9
// Padded spatial size H = 137. Spectral truncation -> direct small DFTs.
// ---------------------------------------------------------------------------

#define NB 16
#define NC 64
#define NH 137
#define NPIX (137*137)      // 18769
#define NM 16
#define NKX 32              // 16 low + 16 high row modes
#define ND 4

static __device__ __align__(16) float g_x[NB*NC*NPIX];     // current field  [b*64+c][x][y]
static __device__ __align__(16) float g_a[NB*NC*NPIX];     // x1 / t scratch
static __device__ __align__(16) float g_Y[NB*NC*32*NH];    // col DFT   [bc][2ky+p][x]
static __device__ __align__(16) float g_Z[NKX*NM*2*NB*NC]; // spectrum  [kx][ky][p][bc]
static __device__ __align__(16) float g_S[NB*NC*NKX*NM*2]; // mixed     [bo][kx][ky][p]
static __device__ __align__(16) float g_U[NB*NC*NH*NM*2];  // inv-row   [bo][x][2ky+p]
static __device__ __align__(16) float g_wm[ND*NKX*NM*2*NC*NC]; // [d][kx][ky][p][i*64+o]
static __device__ __align__(16) float g_F[2*NM*NH];        // fwd col: cos / -sin
static __device__ __align__(16) float g_G[2*NKX*NH];       // fwd row: cos / -sin
static __device__ __align__(16) float g_E[2*NKX*NH];       // inv row: cos / +sin
static __device__ __align__(16) float g_CCt[NM*NH];        // inv col: wgt*norm*cos
static __device__ __align__(16) float g_CSt[NM*NH];        // inv col: wgt*norm*sin

__device__ __forceinline__ float gelu_f(float v) {
    return 0.5f * v * (1.0f + erff(v * 0.70710678118654752440f));
}

// ---------------- twiddle tables (double-precision sincos) -----------------
__global__ void k_tables() {
    int idx = blockIdx.x * blockDim.x + threadIdx.x;
    if (idx >= NKX * NH) return;
    int j = idx / NH, t = idx - j * NH;
    int gk = (j < NM) ? j : (NH - NKX + j);   // 0..15, 121..136
    const double TWO_PI = 6.283185307179586476925286766559;
    double th = TWO_PI * (double)gk * (double)t / (double)NH;
    double s, c;
    sincos(th, &s, &c);
    g_G[(2*j)*NH + t]   = (float)c;
    g_G[(2*j+1)*NH + t] = (float)(-s);
    g_E[(2*j)*NH + t]   = (float)c;
    g_E[(2*j+1)*NH + t] = (float)(s);
    if (j < NM) {
        g_F[(2*j)*NH + t]   = (float)c;
        g_F[(2*j+1)*NH + t] = (float)(-s);
        double wgt = ((j == 0) ? 1.0 : 2.0) / ((double)NH * (double)NH);
        g_CCt[j*NH + t] = (float)(wgt * c);
        g_CSt[j*NH + t] = (float)(wgt * s);
    }
}

// ------------- spectral weight transpose: [d][p][i][o][mx][my] -> wm -------
__global__ void k_wt(const float* __restrict__ sw1, const float* __restrict__ sw2) {
    __shared__ float tile[32][33];
    int d   = blockIdx.z >> 2;
    int p   = (blockIdx.z >> 1) & 1;
    int arr = blockIdx.z & 1;
    const float* src = (arr ? sw2 : sw1) + (size_t)(d*2 + p) * 4096 * 256;
    int mxy = blockIdx.x * 32 + threadIdx.x;
    int io  = blockIdx.y * 32 + threadIdx.y;
    tile[threadIdx.y][threadIdx.x] = src[(size_t)io * 256 + mxy];
    __syncthreads();
    int mxy2 = blockIdx.x * 32 + threadIdx.y;
    int io2  = blockIdx.y * 32 + threadIdx.x;
    g_wm[((size_t)(d*512 + arr*256 + mxy2) * 2 + p) * 4096 + io2] = tile[threadIdx.x][threadIdx.y];
}

// ---------------- embed: concat grids, project 7->64, zero-pad -------------
__global__ __launch_bounds__(160) void k_embed(const float* __restrict__ xin,
                                               const float* __restrict__ pw,
                                               const float* __restrict__ pb) {
    __shared__ float spw[448];
    __shared__ float spb[64];
    int tid = threadIdx.x;
    for (int j = tid; j < 448; j += 160) spw[j] = pw[j];
    if (tid < 64) spb[tid] = pb[tid];
    __syncthreads();
    int b = blockIdx.y, x = blockIdx.x, y = tid;
    if (y >= NH) return;
    bool interior = (x < 128 && y < 128);
    float c[5]; float gx = 0.f, gy = 0.f;
    if (interior) {
        const float* src = xin + ((size_t)(b*5) * 128 + x) * 128 + y;
        #pragma unroll
        for (int i = 0; i < 5; i++) c[i] = src[(size_t)i * 128 * 128];
        const float step = 1.0f / 127.0f;
        gx = x * step; gy = y * step;
    }
    float* dst = g_x + ((size_t)(b*64) * NH + x) * NH + y;
    #pragma unroll 4
    for (int dd = 0; dd < 64; dd++) {
        float s = 0.f;
        if (interior) {
            s = spb[dd];
            #pragma unroll
            for (int i = 0; i < 5; i++) s += c[i] * spw[i*64 + dd];
            s += gx * spw[5*64 + dd] + gy * spw[6*64 + dd];
        }
        dst[(size_t)dd * NPIX] = s;
    }
}

// ---------------- forward column DFT over y: 16 complex modes --------------
__global__ __launch_bounds__(1024) void k_coldft() {
    __shared__ float sx[32][NH];
    __shared__ float sf[32*NH];
    __shared__ float so[32][33];
    int bc = blockIdx.y;
    int x0 = blockIdx.x * 32;
    int tid = threadIdx.x;
    const float* xin = g_x + (size_t)bc * NPIX;
    for (int idx = tid; idx < 32*NH; idx += 1024) {
        int r = idx / NH, y = idx - r*NH;
        int xr = x0 + r;
        sx[r][y] = (xr < NH) ? xin[(size_t)xr*NH + y] : 0.0f;
        sf[idx] = g_F[idx];
    }
    __syncthreads();
    int r = tid >> 5, cc = tid & 31;
    const float* fr = sf + cc*NH;
    const float* xr = sx[r];
    float acc = 0.f;
    #pragma unroll 4
    for (int y = 0; y < NH; y++) acc += xr[y] * fr[y];
    so[r][cc] = acc;
    __syncthreads();
    int c2 = tid >> 5, r2 = tid & 31;
    if (x0 + r2 < NH) g_Y[((size_t)bc*32 + c2)*NH + x0 + r2] = so[r2][c2];
}

// ---------------- forward row DFT over x: 32 complex row modes --------------
__global__ __launch_bounds__(256) void k_rowdft() {
    __shared__ float yr[8*NH], yi[8*NH];
    __shared__ float gc[NKX*NH], gs[NKX*NH];
    int R0 = blockIdx.x * 8;
    int bc = R0 >> 4;
    int ky0 = R0 & 15;
    int tid = threadIdx.x;
    for (int idx = tid; idx < 8*NH; idx += 256) {
        int rr = idx / NH, x = idx - rr*NH;
        int ky = ky0 + rr;
        yr[idx] = g_Y[((size_t)bc*32 + 2*ky)*NH + x];
        yi[idx] = g_Y[((size_t)bc*32 + 2*ky + 1)*NH + x];
    }
    for (int idx = tid; idx < NKX*NH; idx += 256) {
        int j = idx / NH;
        gc[idx] = g_G[idx + j*NH];
        gs[idx] = g_G[idx + (j+1)*NH];
    }
    __syncthreads();
    int rr = tid >> 5, c = tid & 31;
    int ky = ky0 + rr;
    const float* ar = yr + rr*NH;  const float* ai = yi + rr*NH;
    const float* br = gc + c*NH;   const float* bi = gs + c*NH;
    float re = 0.f, im = 0.f;
    #pragma unroll 4
    for (int x = 0; x < NH; x++) {
        float a = ar[x], b = ai[x], cr = br[x], ci = bi[x];
        re += a*cr - b*ci;
        im += a*ci + b*cr;
    }
    g_Z[((c*16 + ky)*2 + 0)*1024 + bc] = re;
    g_Z[((c*16 + ky)*2 + 1)*1024 + bc] = im;
}

// ---------------- spectral channel mix: complex 64x64 per (kx,ky) ----------
__global__ __launch_bounds__(256) void k_mix(int d) {
    __shared__ float zr[1024], zi[1024];
    __shared__ float wr[4096], wi[4096];
    int kk = blockIdx.x;      // kx*16+ky
    int tid = threadIdx.x;
    const float* wb = g_wm + ((size_t)(d*512 + kk) * 2) * 4096;
    for (int idx = tid; idx < 1024; idx += 256) {
        zr[idx] = g_Z[(size_t)(kk*2)*1024 + idx];
        zi[idx] = g_Z[(size_t)(kk*2 + 1)*1024 + idx];
    }
    for (int idx = tid; idx < 4096; idx += 256) {
        wr[idx] = wb[idx];
        wi[idx] = wb[4096 + idx];
    }
    __syncthreads();
    int kx = kk >> 4, ky = kk & 15;
    for (int u = tid; u < 1024; u += 256) {
        int b = u >> 6, o = u & 63;
        const float* zrb = zr + b*64;
        const float* zib = zi + b*64;
        float re = 0.f, im = 0.f;
        #pragma unroll 4
        for (int i = 0; i < 64; i++) {
            float a = zrb[i], bb = zib[i], cr = wr[i*64 + o], ci = wi[i*64 + o];
            re += a*cr - bb*ci;
            im += a*ci + bb*cr;
        }
        size_t off = (size_t)u*1024 + kx*32 + ky*2;
        g_S[off] = re; g_S[off + 1] = im;
    }
}

// ---------------- inverse row transform: 32 modes -> 137 x values ----------
__global__ __launch_bounds__(256) void k_invrow() {
    __shared__ float sr[512], si[512];
    __shared__ float ec[NKX*NH], es[NKX*NH];
    int bo = blockIdx.x, tid = threadIdx.x;
    for (int q = tid; q < 512; q += 256) {
        float2 v = *(const float2*)(g_S + (size_t)bo*1024 + 2*q);
        sr[q] = v.x; si[q] = v.y;
    }
    for (int idx = tid; idx < NKX*NH; idx += 256) {
        int j = idx / NH;
        ec[idx] = g_E[idx + j*NH];
        es[idx] = g_E[idx + (j+1)*NH];
    }
    __syncthreads();
    for (int idx = tid; idx < NH*NM; idx += 256) {
        int x = idx >> 4, ky = idx & 15;
        float re = 0.f, im = 0.f;
        #pragma unroll 4
        for (int k = 0; k < 32; k++) {
            float a = sr[k*16 + ky], b = si[k*16 + ky];
            float c = ec[k*NH + x],  dd = es[k*NH + x];
            re += a*c - b*dd;
            im += a*dd + b*c;
        }
        float2 v; v.x = re; v.y = im;
        *(float2*)(g_U + ((size_t)bo*NH + x)*32 + 2*ky) = v;
    }
}

// ---------------- inverse column transform (hermitian irfft over y) --------
__global__ __launch_bounds__(256) void k_invcol() {
    __shared__ float su[NH*32];
    __shared__ float cc[NM*NH], cs[NM*NH];
    int bo = blockIdx.x, tid = threadIdx.x;
    for (int idx = tid; idx < NH*32; idx += 256) su[idx] = g_U[(size_t)bo*NH*32 + idx];
    for (int idx = tid; idx < NM*NH; idx += 256) { cc[idx] = g_CCt[idx]; cs[idx] = g_CSt[idx]; }
    __syncthreads();
    for (int idx = tid; idx < NPIX; idx += 256) {
        int x = idx / NH, y = idx - x*NH;
        const float* up = su + x*32;
        float acc = 0.f;
        #pragma unroll
        for (int ky = 0; ky < 16; ky++) {
            acc += up[2*ky] * cc[ky*NH + y] - up[2*ky+1] * cs[ky*NH + y];
        }
        g_a[(size_t)bo*NPIX + idx] = acc;
    }
}

// ---------------- conv1x1 (mlp1) + exact gelu, in-place on g_a -------------
__global__ __launch_bounds__(256) void k_mlp1(const float* __restrict__ w,
                                              const float* __restrict__ bias, int d) {
    __shared__ __align__(16) float swT[4096];   // [i*64+o]
    __shared__ float sb[64];
    int tid = threadIdx.x;
    const float* wsrc = w + (size_t)d*4096;     // (o,i)
    for (int j = tid; j < 4096; j += 256) swT[j] = wsrc[(j & 63)*64 + (j >> 6)];
    if (tid < 64) sb[tid] = bias[d*64 + tid];
    __syncthreads();
    int b = blockIdx.y;
    int p = blockIdx.x*256 + tid;
    if (p >= NPIX) return;
    float acc[64];
    #pragma unroll
    for (int o = 0; o < 64; o++) acc[o] = sb[o];
    float* base = g_a + (size_t)b*64*NPIX + p;
    float a = base[0];
    for (int i = 0; i < 64; i++) {
        float an = (i < 63) ? base[(size_t)(i+1)*NPIX] : 0.0f;
        const float4* w4 = (const float4*)(swT + i*64);
        #pragma unroll
        for (int o4 = 0; o4 < 16; o4++) {
            float4 ww = w4[o4];
            acc[o4*4+0] += ww.x * a;
            acc[o4*4+1] += ww.y * a;
            acc[o4*4+2] += ww.z * a;
            acc[o4*4+3] += ww.w * a;
        }
        a = an;
    }
    #pragma unroll
    for (int o = 0; o < 64; o++) base[(size_t)o*NPIX] = gelu_f(acc[o]);
}

// -------- fused conv1x1 (mlp2) + skip conv (ww) + gelu, writes g_x ---------
__global__ __launch_bounds__(256) void k_mlp2(const float* __restrict__ w2,
                                              const float* __restrict__ b2,
                                              const float* __restrict__ wwp,
                                              const float* __restrict__ wbp, int d) {
    __shared__ __align__(16) float s2[4096];  // mlp2 transposed [i*64+o]
    __shared__ __align__(16) float s3[4096];  // ww   transposed [i*64+o]
    __shared__ float sb[64];
    int tid = threadIdx.x;
    const float* w2s = w2 + (size_t)d*4096;
    const float* w3s = wwp + (size_t)d*4096;
    for (int j = tid; j < 4096; j += 256) {
        int o = j & 63, i = j >> 6;
        s2[j] = w2s[o*64 + i];
        s3[j] = w3s[o*64 + i];
    }
    if (tid < 64) sb[tid] = b2[d*64 + tid] + wbp[d*64 + tid];
    __syncthreads();
    int b = blockIdx.y;
    int p = blockIdx.x*256 + tid;
    if (p >= NPIX) return;
    float acc[64];
    #pragma unroll
    for (int o = 0; o < 64; o++) acc[o] = sb[o];
    const float* asrc = g_a + (size_t)b*64*NPIX + p;
    float* xsrc = g_x + (size_t)b*64*NPIX + p;
    float av = asrc[0], xv = xsrc[0];
    for (int i = 0; i < 64; i++) {
        float an = (i < 63) ? asrc[(size_t)(i+1)*NPIX] : 0.0f;
        float xn = (i < 63) ? xsrc[(size_t)(i+1)*NPIX] : 0.0f;
        const float4* wa = (const float4*)(s2 + i*64);
        const float4* wb4 = (const float4*)(s3 + i*64);
        #pragma unroll
        for (int o4 = 0; o4 < 16; o4++) {
            float4 wwa = wa[o4];
            float4 wwb = wb4[o4];
            acc[o4*4+0] += wwa.x*av + wwb.x*xv;
            acc[o4*4+1] += wwa.y*av + wwb.y*xv;
            acc[o4*4+2] += wwa.z*av + wwb.z*xv;
            acc[o4*4+3] += wwa.w*av + wwb.w*xv;
        }
        av = an; xv = xn;
    }
    #pragma unroll
    for (int o = 0; o < 64; o++) xsrc[(size_t)o*NPIX] = gelu_f(acc[o]);
}

// -------- head: crop + q1(64->256) + gelu + q2(256->1), two m-halves -------
__global__ __launch_bounds__(256) void k_head(const float* __restrict__ q1w,
                                              const float* __restrict__ q1b,
                                              const float* __restrict__ q2w,
                                              const float* __restrict__ q2b,
                                              float* __restrict__ out) {
    __shared__ __align__(16) float sw[8192];
    __shared__ float sb1[128], s2[128];
    int tid = threadIdx.x, b = blockIdx.y;
    int idx = blockIdx.x*256 + tid;          // < 16384 always
    int x = idx >> 7, y = idx & 127;
    const float* src = g_x + (size_t)b*64*NPIX + x*NH + y;
    float v[64];
    #pragma unroll
    for (int i = 0; i < 64; i++) v[i] = src[(size_t)i*NPIX];
    float o = q2b[0];
    for (int half = 0; half < 2; half++) {
        __syncthreads();
        for (int j = tid; j < 8192; j += 256) sw[j] = q1w[half*8192 + j];
        if (tid < 128) { sb1[tid] = q1b[half*128 + tid]; s2[tid] = q2w[half*128 + tid]; }
        __syncthreads();
        for (int m = 0; m < 128; m++) {
            float h0 = sb1[m], h1 = 0.f, h2 = 0.f, h3 = 0.f;
            const float4* w4 = (const float4*)(sw + m*64);
            #pragma unroll
            for (int i4 = 0; i4 < 16; i4++) {
                float4 ww = w4[i4];
                h0 += ww.x * v[i4*4+0];
                h1 += ww.y * v[i4*4+1];
                h2 += ww.z * v[i4*4+2];
                h3 += ww.w * v[i4*4+3];
            }
            o += s2[m] * gelu_f((h0 + h1) + (h2 + h3));
        }
    }
    out[(size_t)b*16384 + idx] = o;
}

// ---------------------------------------------------------------------------
extern "C" void kernel_launch(void* const* d_in, const int* in_sizes, int n_in,
                              void* d_out, int out_size) {
    const float* x   = (const float*)d_in[0];
    const float* p_w = (const float*)d_in[1];
    const float* p_b = (const float*)d_in[2];
    const float* sw1 = (const float*)d_in[3];
    const float* sw2 = (const float*)d_in[4];
    const float* m1w = (const float*)d_in[5];
    const float* m1b = (const float*)d_in[6];
    const float* m2w = (const float*)d_in[7];
    const float* m2b = (const float*)d_in[8];
    const float* wwp = (const float*)d_in[9];
    const float* wbp = (const float*)d_in[10];
    const float* q1w = (const float*)d_in[11];
    const float* q1b = (const float*)d_in[12];
    const float* q2w = (const float*)d_in[13];
    const float* q2b = (const float*)d_in[14];
    float* out = (float*)d_out;

    k_tables<<<18, 256>>>();
    k_wt<<<dim3(8, 128, 16), dim3(32, 32)>>>(sw1, sw2);
    k_embed<<<dim3(137, 16), 160>>>(x, p_w, p_b);

    for (int d = 0; d < ND; d++) {
        k_coldft<<<dim3(5, NB*NC), 1024>>>();
        k_rowdft<<<(NB*NC*NM)/8, 256>>>();
        k_mix<<<NKX*NM, 256>>>(d);
        k_invrow<<<NB*NC, 256>>>();
        k_invcol<<<NB*NC, 256>>>();
        k_mlp1<<<dim3((NPIX + 255)/256, NB), 256>>>(m1w, m1b, d);
        k_mlp2<<<dim3((NPIX + 255)/256, NB), 256>>>(m2w, m2b, wwp, wbp, d);
    }

    k_head<<<dim3(64, NB), 256>>>(q1w, q1b, q2w, q2b, out);
}

// round 2
// speedup vs baseline: 1.0058x; 1.0058x over previous
#include <cuda_runtime.h>
#include <math.h>

// ---------------------------------------------------------------------------
// FNO2d: B=16, Cin=5, S=128, W=64 channels, M=16 modes, D=4 layers, PAD=9
// Padded spatial size H = 137. Spectral truncation -> direct small DFTs.
// ---------------------------------------------------------------------------

#define NB 16
#define NC 64
#define NH 137
#define NPIX (137*137)      // 18769
#define NM 16
#define NKX 32              // 16 low + 16 high row modes
#define ND 4

static __device__ __align__(16) float g_x[NB*NC*NPIX];     // current field  [b*64+c][x][y]
static __device__ __align__(16) float g_a[NB*NC*NPIX];     // x1 / t scratch
static __device__ __align__(16) float g_Y[NB*NC*32*NH];    // col DFT   [bc][2ky+p][x]
static __device__ __align__(16) float g_Z[NKX*NM*2*NB*NC]; // spectrum  [kx][ky][p][bc]
static __device__ __align__(16) float g_S[NB*NC*NKX*NM*2]; // mixed     [bo][kx][ky][p]
static __device__ __align__(16) float g_U[NB*NC*NH*NM*2];  // inv-row   [bo][x][2ky+p]
static __device__ __align__(16) float g_wm[ND*NKX*NM*2*NC*NC]; // [d][kx][ky][p][i*64+o]
static __device__ __align__(16) float g_F[2*NM*NH];        // fwd col: cos / -sin
static __device__ __align__(16) float g_G[2*NKX*NH];       // fwd row: cos / -sin
static __device__ __align__(16) float g_E[2*NKX*NH];       // inv row: cos / +sin
static __device__ __align__(16) float g_CCt[NM*NH];        // inv col: wgt*norm*cos
static __device__ __align__(16) float g_CSt[NM*NH];        // inv col: wgt*norm*sin

__device__ __forceinline__ float gelu_f(float v) {
    return 0.5f * v * (1.0f + erff(v * 0.70710678118654752440f));
}

// ---------------- twiddle tables (double-precision sincos) -----------------
__global__ void k_tables() {
    int idx = blockIdx.x * blockDim.x + threadIdx.x;
    if (idx >= NKX * NH) return;
    int j = idx / NH, t = idx - j * NH;
    int gk = (j < NM) ? j : (NH - NKX + j);   // 0..15, 121..136
    const double TWO_PI = 6.283185307179586476925286766559;
    double th = TWO_PI * (double)gk * (double)t / (double)NH;
    double s, c;
    sincos(th, &s, &c);
    g_G[(2*j)*NH + t]   = (float)c;
    g_G[(2*j+1)*NH + t] = (float)(-s);
    g_E[(2*j)*NH + t]   = (float)c;
    g_E[(2*j+1)*NH + t] = (float)(s);
    if (j < NM) {
        g_F[(2*j)*NH + t]   = (float)c;
        g_F[(2*j+1)*NH + t] = (float)(-s);
        double wgt = ((j == 0) ? 1.0 : 2.0) / ((double)NH * (double)NH);
        g_CCt[j*NH + t] = (float)(wgt * c);
        g_CSt[j*NH + t] = (float)(wgt * s);
    }
}

// ------------- spectral weight transpose: [d][p][i][o][mx][my] -> wm -------
__global__ void k_wt(const float* __restrict__ sw1, const float* __restrict__ sw2) {
    __shared__ float tile[32][33];
    int d   = blockIdx.z >> 2;
    int p   = (blockIdx.z >> 1) & 1;
    int arr = blockIdx.z & 1;
    const float* src = (arr ? sw2 : sw1) + (size_t)(d*2 + p) * 4096 * 256;
    int mxy = blockIdx.x * 32 + threadIdx.x;
    int io  = blockIdx.y * 32 + threadIdx.y;
    tile[threadIdx.y][threadIdx.x] = src[(size_t)io * 256 + mxy];
    __syncthreads();
    int mxy2 = blockIdx.x * 32 + threadIdx.y;
    int io2  = blockIdx.y * 32 + threadIdx.x;
    g_wm[((size_t)(d*512 + arr*256 + mxy2) * 2 + p) * 4096 + io2] = tile[threadIdx.x][threadIdx.y];
}

// ---------------- embed: concat grids, project 7->64, zero-pad -------------
__global__ __launch_bounds__(160) void k_embed(const float* __restrict__ xin,
                                               const float* __restrict__ pw,
                                               const float* __restrict__ pb) {
    __shared__ float spw[448];
    __shared__ float spb[64];
    int tid = threadIdx.x;
    for (int j = tid; j < 448; j += 160) spw[j] = pw[j];
    if (tid < 64) spb[tid] = pb[tid];
    __syncthreads();
    int b = blockIdx.y, x = blockIdx.x, y = tid;
    if (y >= NH) return;
    bool interior = (x < 128 && y < 128);
    float c[5]; float gx = 0.f, gy = 0.f;
    if (interior) {
        const float* src = xin + ((size_t)(b*5) * 128 + x) * 128 + y;
        #pragma unroll
        for (int i = 0; i < 5; i++) c[i] = src[(size_t)i * 128 * 128];
        const float step = 1.0f / 127.0f;
        gx = x * step; gy = y * step;
    }
    float* dst = g_x + ((size_t)(b*64) * NH + x) * NH + y;
    #pragma unroll 4
    for (int dd = 0; dd < 64; dd++) {
        float s = 0.f;
        if (interior) {
            s = spb[dd];
            #pragma unroll
            for (int i = 0; i < 5; i++) s += c[i] * spw[i*64 + dd];
            s += gx * spw[5*64 + dd] + gy * spw[6*64 + dd];
        }
        dst[(size_t)dd * NPIX] = s;
    }
}

// ---------------- forward column DFT over y: 16 complex modes --------------
__global__ __launch_bounds__(1024) void k_coldft() {
    __shared__ float sx[32][NH];
    __shared__ float sf[32*NH];
    __shared__ float so[32][33];
    int bc = blockIdx.y;
    int x0 = blockIdx.x * 32;
    int tid = threadIdx.x;
    const float* xin = g_x + (size_t)bc * NPIX;
    for (int idx = tid; idx < 32*NH; idx += 1024) {
        int r = idx / NH, y = idx - r*NH;
        int xr = x0 + r;
        sx[r][y] = (xr < NH) ? xin[(size_t)xr*NH + y] : 0.0f;
        sf[idx] = g_F[idx];
    }
    __syncthreads();
    int r = tid >> 5, cc = tid & 31;
    const float* fr = sf + cc*NH;
    const float* xr = sx[r];
    float acc = 0.f;
    #pragma unroll 4
    for (int y = 0; y < NH; y++) acc += xr[y] * fr[y];
    so[r][cc] = acc;
    __syncthreads();
    int c2 = tid >> 5, r2 = tid & 31;
    if (x0 + r2 < NH) g_Y[((size_t)bc*32 + c2)*NH + x0 + r2] = so[r2][c2];
}

// ---------------- forward row DFT over x: 32 complex row modes --------------
__global__ __launch_bounds__(256) void k_rowdft() {
    __shared__ float yr[8*NH], yi[8*NH];
    __shared__ float gc[NKX*NH], gs[NKX*NH];
    int R0 = blockIdx.x * 8;
    int bc = R0 >> 4;
    int ky0 = R0 & 15;
    int tid = threadIdx.x;
    for (int idx = tid; idx < 8*NH; idx += 256) {
        int rr = idx / NH, x = idx - rr*NH;
        int ky = ky0 + rr;
        yr[idx] = g_Y[((size_t)bc*32 + 2*ky)*NH + x];
        yi[idx] = g_Y[((size_t)bc*32 + 2*ky + 1)*NH + x];
    }
    for (int idx = tid; idx < NKX*NH; idx += 256) {
        int j = idx / NH;
        gc[idx] = g_G[idx + j*NH];
        gs[idx] = g_G[idx + (j+1)*NH];
    }
    __syncthreads();
    int rr = tid >> 5, c = tid & 31;
    int ky = ky0 + rr;
    const float* ar = yr + rr*NH;  const float* ai = yi + rr*NH;
    const float* br = gc + c*NH;   const float* bi = gs + c*NH;
    float re = 0.f, im = 0.f;
    #pragma unroll 4
    for (int x = 0; x < NH; x++) {
        float a = ar[x], b = ai[x], cr = br[x], ci = bi[x];
        re += a*cr - b*ci;
        im += a*ci + b*cr;
    }
    g_Z[((c*16 + ky)*2 + 0)*1024 + bc] = re;
    g_Z[((c*16 + ky)*2 + 1)*1024 + bc] = im;
}

// ---------------- spectral channel mix: complex 64x64 per (kx,ky) ----------
__global__ __launch_bounds__(256) void k_mix(int d) {
    __shared__ float zr[1024], zi[1024];
    __shared__ float wr[4096], wi[4096];
    int kk = blockIdx.x;      // kx*16+ky
    int tid = threadIdx.x;
    const float* wb = g_wm + ((size_t)(d*512 + kk) * 2) * 4096;
    for (int idx = tid; idx < 1024; idx += 256) {
        zr[idx] = g_Z[(size_t)(kk*2)*1024 + idx];
        zi[idx] = g_Z[(size_t)(kk*2 + 1)*1024 + idx];
    }
    for (int idx = tid; idx < 4096; idx += 256) {
        wr[idx] = wb[idx];
        wi[idx] = wb[4096 + idx];
    }
    __syncthreads();
    int kx = kk >> 4, ky = kk & 15;
    for (int u = tid; u < 1024; u += 256) {
        int b = u >> 6, o = u & 63;
        const float* zrb = zr + b*64;
        const float* zib = zi + b*64;
        float re = 0.f, im = 0.f;
        #pragma unroll 4
        for (int i = 0; i < 64; i++) {
            float a = zrb[i], bb = zib[i], cr = wr[i*64 + o], ci = wi[i*64 + o];
            re += a*cr - bb*ci;
            im += a*ci + bb*cr;
        }
        size_t off = (size_t)u*1024 + kx*32 + ky*2;
        g_S[off] = re; g_S[off + 1] = im;
    }
}

// ---------------- inverse row transform: 32 modes -> 137 x values ----------
__global__ __launch_bounds__(256) void k_invrow() {
    __shared__ float sr[512], si[512];
    __shared__ float ec[NKX*NH], es[NKX*NH];
    int bo = blockIdx.x, tid = threadIdx.x;
    for (int q = tid; q < 512; q += 256) {
        float2 v = *(const float2*)(g_S + (size_t)bo*1024 + 2*q);
        sr[q] = v.x; si[q] = v.y;
    }
    for (int idx = tid; idx < NKX*NH; idx += 256) {
        int j = idx / NH;
        ec[idx] = g_E[idx + j*NH];
        es[idx] = g_E[idx + (j+1)*NH];
    }
    __syncthreads();
    for (int idx = tid; idx < NH*NM; idx += 256) {
        int x = idx >> 4, ky = idx & 15;
        float re = 0.f, im = 0.f;
        #pragma unroll 4
        for (int k = 0; k < 32; k++) {
            float a = sr[k*16 + ky], b = si[k*16 + ky];
            float c = ec[k*NH + x],  dd = es[k*NH + x];
            re += a*c - b*dd;
            im += a*dd + b*c;
        }
        float2 v; v.x = re; v.y = im;
        *(float2*)(g_U + ((size_t)bo*NH + x)*32 + 2*ky) = v;
    }
}

// ---------------- inverse column transform (hermitian irfft over y) --------
__global__ __launch_bounds__(256) void k_invcol() {
    __shared__ float su[NH*32];
    __shared__ float cc[NM*NH], cs[NM*NH];
    int bo = blockIdx.x, tid = threadIdx.x;
    for (int idx = tid; idx < NH*32; idx += 256) su[idx] = g_U[(size_t)bo*NH*32 + idx];
    for (int idx = tid; idx < NM*NH; idx += 256) { cc[idx] = g_CCt[idx]; cs[idx] = g_CSt[idx]; }
    __syncthreads();
    for (int idx = tid; idx < NPIX; idx += 256) {
        int x = idx / NH, y = idx - x*NH;
        const float* up = su + x*32;
        float acc = 0.f;
        #pragma unroll
        for (int ky = 0; ky < 16; ky++) {
            acc += up[2*ky] * cc[ky*NH + y] - up[2*ky+1] * cs[ky*NH + y];
        }
        g_a[(size_t)bo*NPIX + idx] = acc;
    }
}

// ---------------- conv1x1 (mlp1) + exact gelu, in-place on g_a -------------
__global__ __launch_bounds__(256) void k_mlp1(const float* __restrict__ w,
                                              const float* __restrict__ bias, int d) {
    __shared__ __align__(16) float swT[4096];   // [i*64+o]
    __shared__ float sb[64];
    int tid = threadIdx.x;
    const float* wsrc = w + (size_t)d*4096;     // (o,i)
    for (int j = tid; j < 4096; j += 256) swT[j] = wsrc[(j & 63)*64 + (j >> 6)];
    if (tid < 64) sb[tid] = bias[d*64 + tid];
    __syncthreads();
    int b = blockIdx.y;
    int p = blockIdx.x*256 + tid;
    if (p >= NPIX) return;
    float acc[64];
    #pragma unroll
    for (int o = 0; o < 64; o++) acc[o] = sb[o];
    float* base = g_a + (size_t)b*64*NPIX + p;
    float a = base[0];
    for (int i = 0; i < 64; i++) {
        float an = (i < 63) ? base[(size_t)(i+1)*NPIX] : 0.0f;
        const float4* w4 = (const float4*)(swT + i*64);
        #pragma unroll
        for (int o4 = 0; o4 < 16; o4++) {
            float4 ww = w4[o4];
            acc[o4*4+0] += ww.x * a;
            acc[o4*4+1] += ww.y * a;
            acc[o4*4+2] += ww.z * a;
            acc[o4*4+3] += ww.w * a;
        }
        a = an;
    }
    #pragma unroll
    for (int o = 0; o < 64; o++) base[(size_t)o*NPIX] = gelu_f(acc[o]);
}

// -------- fused conv1x1 (mlp2) + skip conv (ww) + gelu, writes g_x ---------
__global__ __launch_bounds__(256) void k_mlp2(const float* __restrict__ w2,
                                              const float* __restrict__ b2,
                                              const float* __restrict__ wwp,
                                              const float* __restrict__ wbp, int d) {
    __shared__ __align__(16) float s2[4096];  // mlp2 transposed [i*64+o]
    __shared__ __align__(16) float s3[4096];  // ww   transposed [i*64+o]
    __shared__ float sb[64];
    int tid = threadIdx.x;
    const float* w2s = w2 + (size_t)d*4096;
    const float* w3s = wwp + (size_t)d*4096;
    for (int j = tid; j < 4096; j += 256) {
        int o = j & 63, i = j >> 6;
        s2[j] = w2s[o*64 + i];
        s3[j] = w3s[o*64 + i];
    }
    if (tid < 64) sb[tid] = b2[d*64 + tid] + wbp[d*64 + tid];
    __syncthreads();
    int b = blockIdx.y;
    int p = blockIdx.x*256 + tid;
    if (p >= NPIX) return;
    float acc[64];
    #pragma unroll
    for (int o = 0; o < 64; o++) acc[o] = sb[o];
    const float* asrc = g_a + (size_t)b*64*NPIX + p;
    float* xsrc = g_x + (size_t)b*64*NPIX + p;
    float av = asrc[0], xv = xsrc[0];
    for (int i = 0; i < 64; i++) {
        float an = (i < 63) ? asrc[(size_t)(i+1)*NPIX] : 0.0f;
        float xn = (i < 63) ? xsrc[(size_t)(i+1)*NPIX] : 0.0f;
        const float4* wa = (const float4*)(s2 + i*64);
        const float4* wb4 = (const float4*)(s3 + i*64);
        #pragma unroll
        for (int o4 = 0; o4 < 16; o4++) {
            float4 wwa = wa[o4];
            float4 wwb = wb4[o4];
            acc[o4*4+0] += wwa.x*av + wwb.x*xv;
            acc[o4*4+1] += wwa.y*av + wwb.y*xv;
            acc[o4*4+2] += wwa.z*av + wwb.z*xv;
            acc[o4*4+3] += wwa.w*av + wwb.w*xv;
        }
        av = an; xv = xn;
    }
    #pragma unroll
    for (int o = 0; o < 64; o++) xsrc[(size_t)o*NPIX] = gelu_f(acc[o]);
}

// -------- head: crop + q1(64->256) + gelu + q2(256->1), two m-halves -------
__global__ __launch_bounds__(256) void k_head(const float* __restrict__ q1w,
                                              const float* __restrict__ q1b,
                                              const float* __restrict__ q2w,
                                              const float* __restrict__ q2b,
                                              float* __restrict__ out) {
    __shared__ __align__(16) float sw[8192];
    __shared__ float sb1[128], s2[128];
    int tid = threadIdx.x, b = blockIdx.y;
    int idx = blockIdx.x*256 + tid;          // < 16384 always
    int x = idx >> 7, y = idx & 127;
    const float* src = g_x + (size_t)b*64*NPIX + x*NH + y;
    float v[64];
    #pragma unroll
    for (int i = 0; i < 64; i++) v[i] = src[(size_t)i*NPIX];
    float o = q2b[0];
    for (int half = 0; half < 2; half++) {
        __syncthreads();
        for (int j = tid; j < 8192; j += 256) sw[j] = q1w[half*8192 + j];
        if (tid < 128) { sb1[tid] = q1b[half*128 + tid]; s2[tid] = q2w[half*128 + tid]; }
        __syncthreads();
        for (int m = 0; m < 128; m++) {
            float h0 = sb1[m], h1 = 0.f, h2 = 0.f, h3 = 0.f;
            const float4* w4 = (const float4*)(sw + m*64);
            #pragma unroll
            for (int i4 = 0; i4 < 16; i4++) {
                float4 ww = w4[i4];
                h0 += ww.x * v[i4*4+0];
                h1 += ww.y * v[i4*4+1];
                h2 += ww.z * v[i4*4+2];
                h3 += ww.w * v[i4*4+3];
            }
            o += s2[m] * gelu_f((h0 + h1) + (h2 + h3));
        }
    }
    out[(size_t)b*16384 + idx] = o;
}

// ---------------------------------------------------------------------------
extern "C" void kernel_launch(void* const* d_in, const int* in_sizes, int n_in,
                              void* d_out, int out_size) {
    const float* x   = (const float*)d_in[0];
    const float* p_w = (const float*)d_in[1];
    const float* p_b = (const float*)d_in[2];
    const float* sw1 = (const float*)d_in[3];
    const float* sw2 = (const float*)d_in[4];
    const float* m1w = (const float*)d_in[5];
    const float* m1b = (const float*)d_in[6];
    const float* m2w = (const float*)d_in[7];
    const float* m2b = (const float*)d_in[8];
    const float* wwp = (const float*)d_in[9];
    const float* wbp = (const float*)d_in[10];
    const float* q1w = (const float*)d_in[11];
    const float* q1b = (const float*)d_in[12];
    const float* q2w = (const float*)d_in[13];
    const float* q2b = (const float*)d_in[14];
    float* out = (float*)d_out;

    k_tables<<<18, 256>>>();
    k_wt<<<dim3(8, 128, 16), dim3(32, 32)>>>(sw1, sw2);
    k_embed<<<dim3(137, 16), 160>>>(x, p_w, p_b);

    for (int d = 0; d < ND; d++) {
        k_coldft<<<dim3(5, NB*NC), 1024>>>();
        k_rowdft<<<(NB*NC*NM)/8, 256>>>();
        k_mix<<<NKX*NM, 256>>>(d);
        k_invrow<<<NB*NC, 256>>>();
        k_invcol<<<NB*NC, 256>>>();
        k_mlp1<<<dim3((NPIX + 255)/256, NB), 256>>>(m1w, m1b, d);
        k_mlp2<<<dim3((NPIX + 255)/256, NB), 256>>>(m2w, m2b, wwp, wbp, d);
    }

    k_head<<<dim3(64, NB), 256>>>(q1w, q1b, q2w, q2b, out);
}

// round 5
// speedup vs baseline: 1.1779x; 1.1711x over previous
#include <cuda_runtime.h>
#include <math.h>

// ---------------------------------------------------------------------------
// FNO2d: B=16, Cin=5, S=128, W=64 channels, M=16 modes, D=4 layers, PAD=9
// Padded spatial size H = 137. Spectral truncation -> register-blocked GEMM DFTs.
// ---------------------------------------------------------------------------

#define NB 16
#define NC 64
#define NH 137
#define NPIX (137*137)      // 18769
#define NM 16
#define NKX 32
#define ND 4
#define NBC (NB*NC)         // 1024

static __device__ __align__(16) float g_x[NBC*NPIX];       // field [bc][x*137+y]
static __device__ __align__(16) float g_a[NBC*NPIX];       // scratch
static __device__ __align__(16) float g_Y[NBC*NH*32];      // col DFT [bc][x][2m+p]
static __device__ __align__(16) float g_Z[512*2*NBC];      // spectrum [kk][p][bc]
static __device__ __align__(16) float g_S[NBC*1024];       // mixed [bo][kx][ky][p]
static __device__ __align__(16) float g_U[NBC*32*NH];      // inv-row [bo][2ky+p][x]
static __device__ __align__(16) float g_wm[ND*512*2*4096]; // [d][kk][p][i*64+o]
static __device__ __align__(16) float g_Ft[NH*32];         // fwd col [y][2m+p]: cos/-sin
static __device__ __align__(16) float g_Gt[NH*64];         // fwd row [x][2kx+p]: cos/-sin
static __device__ __align__(16) float g_Et[32*2*NH];       // inv row [kx][2x+p]: cos/+sin
static __device__ __align__(16) float g_Tt[NH*32];         // inv col [y][2ky+p]: w*cos/-w*sin

__device__ __forceinline__ float gelu_f(float v) {
    return 0.5f * v * (1.0f + erff(v * 0.70710678118654752440f));
}

// ---------------- twiddle tables (double-precision sincos) -----------------
__global__ void k_tables() {
    int idx = blockIdx.x * blockDim.x + threadIdx.x;
    if (idx >= NKX * NH) return;
    int j = idx / NH, t = idx - j * NH;
    int gk = (j < NM) ? j : (NH - NKX + j);   // 0..15, 121..136
    const double TWO_PI = 6.283185307179586476925286766559;
    double th = TWO_PI * (double)gk * (double)t / (double)NH;
    double s, c;
    sincos(th, &s, &c);
    g_Gt[t*64 + 2*j]     = (float)c;
    g_Gt[t*64 + 2*j + 1] = (float)(-s);
    g_Et[j*(2*NH) + 2*t]     = (float)c;
    g_Et[j*(2*NH) + 2*t + 1] = (float)(s);
    if (j < NM) {
        g_Ft[t*32 + 2*j]     = (float)c;
        g_Ft[t*32 + 2*j + 1] = (float)(-s);
        double wgt = ((j == 0) ? 1.0 : 2.0) / ((double)NH * (double)NH);
        g_Tt[t*32 + 2*j]     = (float)(wgt * c);
        g_Tt[t*32 + 2*j + 1] = (float)(-wgt * s);
    }
}

// ------------- spectral weight transpose: [d][p][i][o][mx][my] -> wm -------
__global__ void k_wt(const float* __restrict__ sw1, const float* __restrict__ sw2) {
    __shared__ float tile[32][33];
    int d   = blockIdx.z >> 2;
    int p   = (blockIdx.z >> 1) & 1;
    int arr = blockIdx.z & 1;
    const float* src = (arr ? sw2 : sw1) + (size_t)(d*2 + p) * 4096 * 256;
    int mxy = blockIdx.x * 32 + threadIdx.x;
    int io  = blockIdx.y * 32 + threadIdx.y;
    tile[threadIdx.y][threadIdx.x] = src[(size_t)io * 256 + mxy];
    __syncthreads();
    int mxy2 = blockIdx.x * 32 + threadIdx.y;
    int io2  = blockIdx.y * 32 + threadIdx.x;
    g_wm[((size_t)(d*512 + arr*256 + mxy2) * 2 + p) * 4096 + io2] = tile[threadIdx.x][threadIdx.y];
}

// ---------------- embed: concat grids, project 7->64, zero-pad -------------
__global__ __launch_bounds__(160) void k_embed(const float* __restrict__ xin,
                                               const float* __restrict__ pw,
                                               const float* __restrict__ pb) {
    __shared__ float spw[448];
    __shared__ float spb[64];
    int tid = threadIdx.x;
    for (int j = tid; j < 448; j += 160) spw[j] = pw[j];
    if (tid < 64) spb[tid] = pb[tid];
    __syncthreads();
    int b = blockIdx.y, x = blockIdx.x, y = tid;
    if (y >= NH) return;
    bool interior = (x < 128 && y < 128);
    float c[5]; float gx = 0.f, gy = 0.f;
    if (interior) {
        const float* src = xin + ((size_t)(b*5) * 128 + x) * 128 + y;
        #pragma unroll
        for (int i = 0; i < 5; i++) c[i] = src[(size_t)i * 128 * 128];
        const float step = 1.0f / 127.0f;
        gx = x * step; gy = y * step;
    }
    float* dst = g_x + ((size_t)(b*64) * NH + x) * NH + y;
    #pragma unroll 4
    for (int dd = 0; dd < 64; dd++) {
        float s = 0.f;
        if (interior) {
            s = spb[dd];
            #pragma unroll
            for (int i = 0; i < 5; i++) s += c[i] * spw[i*64 + dd];
            s += gx * spw[5*64 + dd] + gy * spw[6*64 + dd];
        }
        dst[(size_t)dd * NPIX] = s;
    }
}

// ------- forward column DFT over y: GEMM C[48x x 32] = X[48x137] F[137x32] ---
__global__ __launch_bounds__(128) void k_coldft() {
    __shared__ __align__(16) float sx[NH*49];   // [y][xr], pad 49 (scalar reads only)
    __shared__ __align__(16) float sf[NH*32];   // [y][2m+p]
    int bc = blockIdx.y;
    int x0 = blockIdx.x * 48;
    int tid = threadIdx.x;
    const float* xin = g_x + (size_t)bc * NPIX;
    for (int idx = tid; idx < 48*NH; idx += 128) {
        int xr = idx / NH, y = idx - xr*NH;
        float v = (x0 + xr < NH) ? xin[(size_t)(x0+xr)*NH + y] : 0.f;
        sx[y*49 + xr] = v;
    }
    for (int idx = tid; idx < NH*32; idx += 128) sf[idx] = g_Ft[idx];
    __syncthreads();
    int tx = tid & 7, ty = tid >> 3;          // 8 col-groups x 16 row-groups
    int r0 = ty*3, c0 = tx*4;                 // 3 rows x 4 cols per thread
    float4 a0 = {0,0,0,0}, a1 = {0,0,0,0}, a2 = {0,0,0,0};
    #pragma unroll 2
    for (int y = 0; y < NH; y++) {
        float4 f = *(const float4*)&sf[y*32 + c0];   // 16B-aligned: c0%4==0
        float v0 = sx[y*49 + r0];
        float v1 = sx[y*49 + r0 + 1];
        float v2 = sx[y*49 + r0 + 2];
        a0.x += v0*f.x; a0.y += v0*f.y; a0.z += v0*f.z; a0.w += v0*f.w;
        a1.x += v1*f.x; a1.y += v1*f.y; a1.z += v1*f.z; a1.w += v1*f.w;
        a2.x += v2*f.x; a2.y += v2*f.y; a2.z += v2*f.z; a2.w += v2*f.w;
    }
    int r = x0 + r0;
    if (r < NH) {
        float* gy = &g_Y[((size_t)bc*NH + r)*32 + c0];
        gy[0] = a0.x; gy[1] = a0.y; gy[2] = a0.z; gy[3] = a0.w;
    }
    if (r + 1 < NH) {
        float* gy = &g_Y[((size_t)bc*NH + r + 1)*32 + c0];
        gy[0] = a1.x; gy[1] = a1.y; gy[2] = a1.z; gy[3] = a1.w;
    }
    if (r + 2 < NH) {
        float* gy = &g_Y[((size_t)bc*NH + r + 2)*32 + c0];
        gy[0] = a2.x; gy[1] = a2.y; gy[2] = a2.z; gy[3] = a2.w;
    }
}

// ------- forward row DFT over x: C[16ky x 32kx] complex, K=137 -------------
__global__ __launch_bounds__(128) void k_rowdft() {
    __shared__ __align__(16) float ys[NH*36];   // [x][2ky+p] pad 36 (36%4==0)
    int bc = blockIdx.x;
    int tid = threadIdx.x;
    for (int idx = tid; idx < NH*32; idx += 128) {
        int x = idx >> 5, c = idx & 31;
        ys[x*36 + c] = g_Y[((size_t)bc*NH + x)*32 + c];
    }
    __syncthreads();
    int tx = tid & 31;            // kx
    int ty = tid >> 5;            // ky group of 4
    float re[4] = {0,0,0,0}, im[4] = {0,0,0,0};
    #pragma unroll 2
    for (int x = 0; x < NH; x++) {
        const float4* yp = (const float4*)&ys[x*36 + ty*8];
        float4 yA = yp[0];                               // re0 im0 re1 im1
        float4 yB = yp[1];                               // re2 im2 re3 im3
        float gc = g_Gt[x*64 + 2*tx];                    // scalar LDG, L1-resident
        float gs = g_Gt[x*64 + 2*tx + 1];
        re[0] += yA.x*gc - yA.y*gs;  im[0] += yA.x*gs + yA.y*gc;
        re[1] += yA.z*gc - yA.w*gs;  im[1] += yA.z*gs + yA.w*gc;
        re[2] += yB.x*gc - yB.y*gs;  im[2] += yB.x*gs + yB.y*gc;
        re[3] += yB.z*gc - yB.w*gs;  im[3] += yB.z*gs + yB.w*gc;
    }
    #pragma unroll
    for (int j = 0; j < 4; j++) {
        int ky = ty*4 + j;
        size_t base = (size_t)((tx*16 + ky)*2)*NBC + bc;
        g_Z[base]       = re[j];
        g_Z[base + NBC] = im[j];
    }
}

// ---------------- spectral channel mix: complex 64x64 per (kx,ky) ----------
__global__ __launch_bounds__(256) void k_mix(int d) {
    __shared__ float zr[1024], zi[1024];
    __shared__ float wr[4096], wi[4096];
    int kk = blockIdx.x;
    int tid = threadIdx.x;
    const float* wb = g_wm + ((size_t)(d*512 + kk) * 2) * 4096;
    for (int idx = tid; idx < 1024; idx += 256) {
        zr[idx] = g_Z[(size_t)(kk*2)*NBC + idx];
        zi[idx] = g_Z[(size_t)(kk*2 + 1)*NBC + idx];
    }
    for (int idx = tid; idx < 4096; idx += 256) {
        wr[idx] = wb[idx];
        wi[idx] = wb[4096 + idx];
    }
    __syncthreads();
    int kx = kk >> 4, ky = kk & 15;
    int o = tid & 63, bg = tid >> 6;          // 4 batches per thread
    float re[4] = {0,0,0,0}, im[4] = {0,0,0,0};
    #pragma unroll 2
    for (int i = 0; i < 64; i++) {
        float wrv = wr[i*64 + o], wiv = wi[i*64 + o];
        #pragma unroll
        for (int jb = 0; jb < 4; jb++) {
            int b = bg*4 + jb;
            float a = zr[b*64 + i], bb = zi[b*64 + i];
            re[jb] += a*wrv - bb*wiv;
            im[jb] += a*wiv + bb*wrv;
        }
    }
    #pragma unroll
    for (int jb = 0; jb < 4; jb++) {
        size_t off = (size_t)((bg*4 + jb)*64 + o)*1024 + kx*32 + ky*2;
        g_S[off] = re[jb]; g_S[off + 1] = im[jb];
    }
}

// ------- inverse row transform: per x, all 16 ky complex, K=32 kx ----------
__global__ __launch_bounds__(160) void k_invrow() {
    __shared__ __align__(16) float ss[1024];        // [kx][2ky+p]
    __shared__ __align__(16) float es[32*2*NH];     // [kx][2x+p]
    int bo = blockIdx.x, tid = threadIdx.x;
    for (int idx = tid; idx < 1024; idx += 160) ss[idx] = g_S[(size_t)bo*1024 + idx];
    for (int idx = tid; idx < 32*2*NH; idx += 160) es[idx] = g_Et[idx];
    __syncthreads();
    int x = tid;
    if (x >= NH) return;
    float re[16], im[16];
    #pragma unroll
    for (int j = 0; j < 16; j++) { re[j] = 0.f; im[j] = 0.f; }
    for (int k = 0; k < 32; k++) {
        float2 e = *(const float2*)&es[k*(2*NH) + 2*x];      // even idx -> 8B aligned
        #pragma unroll
        for (int ky = 0; ky < 16; ky++) {
            float2 s = *(const float2*)&ss[k*32 + 2*ky];     // broadcast
            re[ky] += s.x*e.x - s.y*e.y;
            im[ky] += s.x*e.y + s.y*e.x;
        }
    }
    float* ub = g_U + (size_t)bo*32*NH;
    #pragma unroll
    for (int ky = 0; ky < 16; ky++) {
        ub[(2*ky)*NH + x]   = re[ky];     // coalesced across x lanes
        ub[(2*ky+1)*NH + x] = im[ky];
    }
}

// ------- inverse column transform: u[32] in regs, lane=y coalesced stores --
__global__ __launch_bounds__(256) void k_invcol() {
    __shared__ __align__(16) float ts[NH*36];   // [y][2ky+p] pad 36
    int bo = blockIdx.y;
    int tid = threadIdx.x;
    for (int idx = tid; idx < NH*32; idx += 256) {
        int y = idx >> 5, c = idx & 31;
        ts[y*36 + c] = g_Tt[idx];
    }
    __syncthreads();
    int ly = tid & 31, xg = tid >> 5;           // 32 y-lanes, 8 x rows per block
    int x = blockIdx.x * 8 + xg;
    if (x >= NH) return;
    const float* ub = g_U + (size_t)bo*32*NH;
    float u[32];
    #pragma unroll
    for (int k = 0; k < 32; k++) u[k] = ub[k*NH + x];   // broadcast LDG per xg
    float* dst = g_a + (size_t)bo*NPIX + (size_t)x*NH;
    for (int y = ly; y < NH; y += 32) {
        const float4* t4 = (const float4*)&ts[y*36];    // (y*36)%4==0 -> 16B aligned
        float acc = 0.f;
        #pragma unroll
        for (int kh = 0; kh < 8; kh++) {
            float4 t = t4[kh];
            acc += u[4*kh]*t.x + u[4*kh+1]*t.y + u[4*kh+2]*t.z + u[4*kh+3]*t.w;
        }
        dst[y] = acc;                                   // coalesced across lanes
    }
}

// ---------------- conv1x1 (mlp1) + exact gelu, in-place on g_a -------------
__global__ __launch_bounds__(256) void k_mlp1(const float* __restrict__ w,
                                              const float* __restrict__ bias, int d) {
    __shared__ __align__(16) float swT[4096];   // [i*64+o]
    __shared__ float sb[64];
    int tid = threadIdx.x;
    const float* wsrc = w + (size_t)d*4096;     // (o,i)
    for (int j = tid; j < 4096; j += 256) swT[j] = wsrc[(j & 63)*64 + (j >> 6)];
    if (tid < 64) sb[tid] = bias[d*64 + tid];
    __syncthreads();
    int b = blockIdx.y;
    int p = blockIdx.x*256 + tid;
    if (p >= NPIX) return;
    float acc[64];
    #pragma unroll
    for (int o = 0; o < 64; o++) acc[o] = sb[o];
    float* base = g_a + (size_t)b*64*NPIX + p;
    float a = base[0];
    for (int i = 0; i < 64; i++) {
        float an = (i < 63) ? base[(size_t)(i+1)*NPIX] : 0.0f;
        const float4* w4 = (const float4*)(swT + i*64);
        #pragma unroll
        for (int o4 = 0; o4 < 16; o4++) {
            float4 ww = w4[o4];
            acc[o4*4+0] += ww.x * a;
            acc[o4*4+1] += ww.y * a;
            acc[o4*4+2] += ww.z * a;
            acc[o4*4+3] += ww.w * a;
        }
        a = an;
    }
    #pragma unroll
    for (int o = 0; o < 64; o++) base[(size_t)o*NPIX] = gelu_f(acc[o]);
}

// -------- fused conv1x1 (mlp2) + skip conv (ww) + gelu, writes g_x ---------
__global__ __launch_bounds__(256) void k_mlp2(const float* __restrict__ w2,
                                              const float* __restrict__ b2,
                                              const float* __restrict__ wwp,
                                              const float* __restrict__ wbp, int d) {
    __shared__ __align__(16) float s2[4096];
    __shared__ __align__(16) float s3[4096];
    __shared__ float sb[64];
    int tid = threadIdx.x;
    const float* w2s = w2 + (size_t)d*4096;
    const float* w3s = wwp + (size_t)d*4096;
    for (int j = tid; j < 4096; j += 256) {
        int o = j & 63, i = j >> 6;
        s2[j] = w2s[o*64 + i];
        s3[j] = w3s[o*64 + i];
    }
    if (tid < 64) sb[tid] = b2[d*64 + tid] + wbp[d*64 + tid];
    __syncthreads();
    int b = blockIdx.y;
    int p = blockIdx.x*256 + tid;
    if (p >= NPIX) return;
    float acc[64];
    #pragma unroll
    for (int o = 0; o < 64; o++) acc[o] = sb[o];
    const float* asrc = g_a + (size_t)b*64*NPIX + p;
    float* xsrc = g_x + (size_t)b*64*NPIX + p;
    float av = asrc[0], xv = xsrc[0];
    for (int i = 0; i < 64; i++) {
        float an = (i < 63) ? asrc[(size_t)(i+1)*NPIX] : 0.0f;
        float xn = (i < 63) ? xsrc[(size_t)(i+1)*NPIX] : 0.0f;
        const float4* wa = (const float4*)(s2 + i*64);
        const float4* wb4 = (const float4*)(s3 + i*64);
        #pragma unroll
        for (int o4 = 0; o4 < 16; o4++) {
            float4 wwa = wa[o4];
            float4 wwb = wb4[o4];
            acc[o4*4+0] += wwa.x*av + wwb.x*xv;
            acc[o4*4+1] += wwa.y*av + wwb.y*xv;
            acc[o4*4+2] += wwa.z*av + wwb.z*xv;
            acc[o4*4+3] += wwa.w*av + wwb.w*xv;
        }
        av = an; xv = xn;
    }
    #pragma unroll
    for (int o = 0; o < 64; o++) xsrc[(size_t)o*NPIX] = gelu_f(acc[o]);
}

// -------- head: crop + q1(64->256) + gelu + q2(256->1), two m-halves -------
__global__ __launch_bounds__(256) void k_head(const float* __restrict__ q1w,
                                              const float* __restrict__ q1b,
                                              const float* __restrict__ q2w,
                                              const float* __restrict__ q2b,
                                              float* __restrict__ out) {
    __shared__ __align__(16) float sw[8192];
    __shared__ float sb1[128], s2[128];
    int tid = threadIdx.x, b = blockIdx.y;
    int idx = blockIdx.x*256 + tid;          // < 16384 always
    int x = idx >> 7, y = idx & 127;
    const float* src = g_x + (size_t)b*64*NPIX + x*NH + y;
    float v[64];
    #pragma unroll
    for (int i = 0; i < 64; i++) v[i] = src[(size_t)i*NPIX];
    float o = q2b[0];
    for (int half = 0; half < 2; half++) {
        __syncthreads();
        for (int j = tid; j < 8192; j += 256) sw[j] = q1w[half*8192 + j];
        if (tid < 128) { sb1[tid] = q1b[half*128 + tid]; s2[tid] = q2w[half*128 + tid]; }
        __syncthreads();
        for (int m = 0; m < 128; m++) {
            float h0 = sb1[m], h1 = 0.f, h2 = 0.f, h3 = 0.f;
            const float4* w4 = (const float4*)(sw + m*64);
            #pragma unroll
            for (int i4 = 0; i4 < 16; i4++) {
                float4 ww = w4[i4];
                h0 += ww.x * v[i4*4+0];
                h1 += ww.y * v[i4*4+1];
                h2 += ww.z * v[i4*4+2];
                h3 += ww.w * v[i4*4+3];
            }
            o += s2[m] * gelu_f((h0 + h1) + (h2 + h3));
        }
    }
    out[(size_t)b*16384 + idx] = o;
}

// ---------------------------------------------------------------------------
extern "C" void kernel_launch(void* const* d_in, const int* in_sizes, int n_in,
                              void* d_out, int out_size) {
    const float* x   = (const float*)d_in[0];
    const float* p_w = (const float*)d_in[1];
    const float* p_b = (const float*)d_in[2];
    const float* sw1 = (const float*)d_in[3];
    const float* sw2 = (const float*)d_in[4];
    const float* m1w = (const float*)d_in[5];
    const float* m1b = (const float*)d_in[6];
    const float* m2w = (const float*)d_in[7];
    const float* m2b = (const float*)d_in[8];
    const float* wwp = (const float*)d_in[9];
    const float* wbp = (const float*)d_in[10];
    const float* q1w = (const float*)d_in[11];
    const float* q1b = (const float*)d_in[12];
    const float* q2w = (const float*)d_in[13];
    const float* q2b = (const float*)d_in[14];
    float* out = (float*)d_out;

    k_tables<<<18, 256>>>();
    k_wt<<<dim3(8, 128, 16), dim3(32, 32)>>>(sw1, sw2);
    k_embed<<<dim3(137, 16), 160>>>(x, p_w, p_b);

    const int mlpblocks = (NPIX + 255) / 256;
    for (int d = 0; d < ND; d++) {
        k_coldft<<<dim3(3, NBC), 128>>>();
        k_rowdft<<<NBC, 128>>>();
        k_mix<<<512, 256>>>(d);
        k_invrow<<<NBC, 160>>>();
        k_invcol<<<dim3(18, NBC), 256>>>();
        k_mlp1<<<dim3(mlpblocks, NB), 256>>>(m1w, m1b, d);
        k_mlp2<<<dim3(mlpblocks, NB), 256>>>(m2w, m2b, wwp, wbp, d);
    }

    k_head<<<dim3(64, NB), 256>>>(q1w, q1b, q2w, q2b, out);
}